// round 6
// baseline (speedup 1.0000x reference)
#include <cuda_runtime.h>

// QConv1D quantum sim, R6: closed-form (Heisenberg / independent-set transfer
// matrix DP) single kernel, latency-tuned:
//  - fast __sincosf everywhere (err ~1e-6 << 1e-3 budget)
//  - 512-thread blocks, 128 blocks -> single wave on 148 SMs
//  - float2 weight loads, x load issued before weight-trig section
constexpr int O_CH  = 8;
constexpr int NQ    = 8;
constexpr int L_IN  = 512;
constexpr int L_OUT = 509;
constexpr int B_SZ  = 16;
constexpr int N_POS = B_SZ * L_OUT;          // 8144
constexpr int TPB   = 512;
constexpr int POS_PER_BLK = TPB / O_CH;      // 64

__global__ __launch_bounds__(TPB)
void qconv_kernel(const float* __restrict__ x,
                  const float* __restrict__ w,
                  float* __restrict__ out)
{
    __shared__ float4 sw[O_CH * NQ];         // {cos p0, sin p0, cos p1, sin p1}

    const int tid = threadIdx.x;

    // --- this thread's sim: position n, out-channel u (issue x load FIRST)
    const int n_raw = blockIdx.x * POS_PER_BLK + (tid >> 3);
    const bool valid = (n_raw < N_POS);
    const int n   = valid ? n_raw : N_POS - 1;
    const int u   = tid & 7;                 // o-channel AND trig-qubit index
    const int bb  = n / L_OUT;
    const int pos = n - bb * L_OUT;
    // lane u holds x-trig for qubit q=u: q<4 -> ch0 off q ; q>=4 -> ch1 off q-4
    const float xv = x[(bb * 2 + (u >> 2)) * L_IN + pos + (u & 3)];

    // --- weight trig (threads 0..63), w layout (O, NQ, 2)
    if (tid < O_CH * NQ) {
        const float2 wv2 = reinterpret_cast<const float2*>(w)[tid];
        float c0, s0, c1, s1;
        __sincosf(wv2.x, &s0, &c0);          // layer 0 param
        __sincosf(wv2.y, &s1, &c1);          // layer 1 param
        sw[tid] = make_float4(c0, s0, c1, s1);
    }

    float sx, cx;
    __sincosf(xv, &sx, &cx);

    __syncthreads();

    const int gbase = (tid & 31) & ~7;       // 8-lane group base within warp
    const float4* __restrict__ wv = sw + u * NQ;

    // --- 3-state transfer-matrix DP over the 8-qubit chain
    float v00 = 1.f, v01 = 1.f, v10 = 0.f;
#pragma unroll
    for (int q = 0; q < NQ; q++) {
        const float cxq = __shfl_sync(0xffffffffu, cx, gbase + q);
        const float sxq = __shfl_sync(0xffffffffu, sx, gbase + q);
        const float4 wq = wv[q];
        const float C  = cxq * wq.x - sxq * wq.y;   // cos(x+p0)
        const float S  = sxq * wq.x + cxq * wq.y;   // sin(x+p0)
        const float uu  = -wq.w * S;                // -sin(p1) sin(x+p0)
        const float n00 = wq.z * fmaf(v00, C, v10);
        const float n01 = wq.z * fmaf(v10, C, v00);
        const float n10 = uu * v01;
        v00 = n00; v01 = n01; v10 = n10;
    }
    const float E = v00 + v10;                      // boundary b_8 = 0

    // --- reference reshape reinterpretation: flat [o][n] read as [b'][p'][o']
    if (valid) {
        const int s  = u * N_POS + n;
        const int oo = s & 7;
        const int tt = s >> 3;
        const int bo = tt / L_OUT;
        const int po = tt - bo * L_OUT;
        out[(bo * O_CH + oo) * L_OUT + po] = E;
    }
}

extern "C" void kernel_launch(void* const* d_in, const int* in_sizes, int n_in,
                              void* d_out, int out_size)
{
    const float* x = (const float*)d_in[0];
    const float* w = (const float*)d_in[1];
    float* out = (float*)d_out;
    const int blocks = (N_POS + POS_PER_BLK - 1) / POS_PER_BLK;   // 128
    qconv_kernel<<<blocks, TPB>>>(x, w, out);
}

// round 7
// speedup vs baseline: 1.2930x; 1.2930x over previous
#include <cuda_runtime.h>

// QConv1D quantum sim, R7: closed-form (Heisenberg / independent-set transfer
// matrix DP) single kernel.
//  R7 deltas: conflict-free padded smem weight table (was 8-way LDS conflict),
//  cheaper output indexing (one cmp instead of a div).
constexpr int O_CH  = 8;
constexpr int NQ    = 8;
constexpr int L_IN  = 512;
constexpr int L_OUT = 509;
constexpr int B_SZ  = 16;
constexpr int N_POS = B_SZ * L_OUT;          // 8144 (multiple of 8)
constexpr int TPB   = 512;
constexpr int POS_PER_BLK = TPB / O_CH;      // 64
constexpr int WPAD  = 9;                     // padded row stride (float4 units)

__global__ __launch_bounds__(TPB)
void qconv_kernel(const float* __restrict__ x,
                  const float* __restrict__ w,
                  float* __restrict__ out)
{
    __shared__ float4 sw[O_CH * WPAD];       // [o*9 + q] = {c0,s0,c1,s1}

    const int tid = threadIdx.x;

    // --- this thread's sim: position n, out-channel u (x load issued FIRST)
    const int n_raw = blockIdx.x * POS_PER_BLK + (tid >> 3);
    const bool valid = (n_raw < N_POS);
    const int n   = valid ? n_raw : N_POS - 1;
    const int u   = tid & 7;                 // o-channel AND trig-qubit index
    const int bb  = n / L_OUT;
    const int pos = n - bb * L_OUT;
    // lane u computes x-trig for qubit q=u: q<4 -> ch0 off q ; q>=4 -> ch1 off q-4
    const float xv = x[(bb * 2 + (u >> 2)) * L_IN + pos + (u & 3)];

    // --- weight trig (threads 0..63), w layout (O, NQ, 2)
    if (tid < O_CH * NQ) {
        const float2 wv2 = reinterpret_cast<const float2*>(w)[tid];
        float c0, s0, c1, s1;
        __sincosf(wv2.x, &s0, &c0);          // layer 0 param
        __sincosf(wv2.y, &s1, &c1);          // layer 1 param
        sw[(tid >> 3) * WPAD + (tid & 7)] = make_float4(c0, s0, c1, s1);
    }

    float sx, cx;
    __sincosf(xv, &sx, &cx);

    __syncthreads();

    const int gbase = (tid & 31) & ~7;       // 8-lane group base within warp
    const float4* __restrict__ wv = sw + u * WPAD;

    // --- 3-state transfer-matrix DP over the 8-qubit chain
    float v00 = 1.f, v01 = 1.f, v10 = 0.f;
#pragma unroll
    for (int q = 0; q < NQ; q++) {
        const float cxq = __shfl_sync(0xffffffffu, cx, gbase + q);
        const float sxq = __shfl_sync(0xffffffffu, sx, gbase + q);
        const float4 wq = wv[q];
        const float C  = cxq * wq.x - sxq * wq.y;   // cos(x+p0)
        const float S  = sxq * wq.x + cxq * wq.y;   // sin(x+p0)
        const float uu  = -wq.w * S;                // -sin(p1) sin(x+p0)
        const float n00 = wq.z * fmaf(v00, C, v10);
        const float n01 = wq.z * fmaf(v10, C, v00);
        const float n10 = uu * v01;
        v00 = n00; v01 = n01; v10 = n10;
    }
    const float E = v00 + v10;                      // boundary b_8 = 0

    // --- output: flat [o][n] buffer reinterpreted by reference as [b'][p'][o']
    //     s = u*8144 + n ; 8144 % 8 == 0 ->
    //       oo = n & 7 ; tt = u*1018 + (n>>3) ; bo = tt/509 = 2u + (n>>3 >= 509)
    if (valid) {
        const int oo = n & 7;
        const int nh = n >> 3;                      // 0..1017
        const int hi = (nh >= L_OUT) ? 1 : 0;
        const int bo = 2 * u + hi;
        const int po = nh - hi * L_OUT;
        out[(bo * O_CH + oo) * L_OUT + po] = E;
    }
}

extern "C" void kernel_launch(void* const* d_in, const int* in_sizes, int n_in,
                              void* d_out, int out_size)
{
    const float* x = (const float*)d_in[0];
    const float* w = (const float*)d_in[1];
    float* out = (float*)d_out;
    const int blocks = (N_POS + POS_PER_BLK - 1) / POS_PER_BLK;   // 128
    qconv_kernel<<<blocks, TPB>>>(x, w, out);
}